// round 4
// baseline (speedup 1.0000x reference)
#include <cuda_runtime.h>
#include <math.h>

#define NBITS   20
#define NSUB    ((1u << NBITS) - 1u)    // 1048575 elements in w
#define NCHUNK  (1 << (NBITS - 5))      // 32768 chunks of 32
#define NBLOCKS 128
#define NTPB    256

// Per-block partial sums + arrival counter. g_part fully overwritten each
// launch; g_count is reset to 0 by the last block each launch (replay-safe).
__device__ float g_part[NBLOCKS][NBITS + 1];
__device__ unsigned int g_count = 0;

__global__ void __launch_bounds__(NTPB) mil_fused_kernel(const float* __restrict__ w,
                                                         const float* __restrict__ yprob,
                                                         const int*   __restrict__ Yp,
                                                         int has_Y,
                                                         float* __restrict__ out) {
    const int tid  = threadIdx.x;
    const int c    = blockIdx.x * NTPB + tid;   // chunk id, 0..32767 (exact cover)
    const int base = c << 5;                    // first element index e of the chunk

    // ---- load 32 elements v[0..31] (e = base+k) ----
    float v[32];
    const float4* __restrict__ w4 = (const float4*)w;
    if (c != NCHUNK - 1) {
#pragma unroll
        for (int g = 0; g < 8; g++) {
            float4 t = w4[(base >> 2) + g];
            v[4*g+0] = t.x; v[4*g+1] = t.y; v[4*g+2] = t.z; v[4*g+3] = t.w;
        }
    } else {
        // last chunk: e = 1048544..1048574 exist; e = 1048575 does not
#pragma unroll
        for (int g = 0; g < 7; g++) {
            float4 t = w4[(base >> 2) + g];
            v[4*g+0] = t.x; v[4*g+1] = t.y; v[4*g+2] = t.z; v[4*g+3] = t.w;
        }
        v[28] = w[base + 28];
        v[29] = w[base + 29];
        v[30] = w[base + 30];
        v[31] = 0.0f;
    }

    // u[j] = w value whose subset index i has low-5-bits == j (i = base+1+k -> j = k+1)
    float u[32];
    u[0] = 0.0f;
#pragma unroll
    for (int j = 1; j < 32; j++) u[j] = v[j - 1];
    const float v31 = v[31];

    // ---- binary partial-sum tree over u ----
    float T1[16], T2[8], T3[4], T4[2];
#pragma unroll
    for (int k = 0; k < 16; k++) T1[k] = u[2*k] + u[2*k+1];
#pragma unroll
    for (int k = 0; k < 8;  k++) T2[k] = T1[2*k] + T1[2*k+1];
#pragma unroll
    for (int k = 0; k < 4;  k++) T3[k] = T2[2*k] + T2[2*k+1];
#pragma unroll
    for (int k = 0; k < 2;  k++) T4[k] = T3[2*k] + T3[2*k+1];
    const float S = T4[0] + T4[1];      // sum of first 31 elements

    // low-bit sums
    float B0 = 0.0f, B1 = 0.0f, B2 = 0.0f, B3 = 0.0f;
#pragma unroll
    for (int j = 1; j < 32; j += 2) B0 += u[j];
#pragma unroll
    for (int k = 1; k < 16; k += 2) B1 += T1[k];
#pragma unroll
    for (int k = 1; k < 8;  k += 2) B2 += T2[k];
    B3 = T3[1] + T3[3];
    const float B4 = T4[1];

    // ---- per-chunk contribution vector p[0..20] ----
    float p[NBITS + 1];
    p[0] = B0; p[1] = B1; p[2] = B2; p[3] = B3; p[4] = B4;
    p[NBITS] = S + v31;

    const unsigned cc = (unsigned)c;
    const unsigned c1 = (unsigned)c + 1u;
    const unsigned sb = __float_as_uint(S);
    const unsigned vb = __float_as_uint(v31);
#pragma unroll
    for (int b = 5; b < NBITS; b++) {
        const int sh = 31 - (b - 5);
        unsigned m1 = (unsigned)(((int)(cc << sh)) >> 31);
        unsigned m2 = (unsigned)(((int)(c1 << sh)) >> 31);
        p[b] = __uint_as_float(sb & m1) + __uint_as_float(vb & m2);
    }

    // ---- block reduction of the 21-vector ----
    __shared__ float red[NTPB][NBITS + 2];   // +1 pad against systematic conflicts
#pragma unroll
    for (int b = 0; b <= NBITS; b++) red[tid][b] = p[b];
    __syncthreads();

#pragma unroll
    for (int s = NTPB / 2; s >= 1; s >>= 1) {
        if (tid < s) {
#pragma unroll
            for (int b = 0; b <= NBITS; b++) red[tid][b] += red[tid + s][b];
        }
        __syncthreads();
    }

    if (tid <= NBITS) g_part[blockIdx.x][tid] = red[0][tid];

    // ---- last-block-done: finalize inside the same launch ----
    __threadfence();
    __shared__ unsigned int s_last;
    if (tid == 0) s_last = atomicAdd(&g_count, 1u);
    __syncthreads();
    if (s_last != NBLOCKS - 1) return;

    // This is the last block. Reset counter for the next (graph-replayed) launch.
    if (tid == 0) g_count = 0;
    __threadfence();   // make all writer blocks' g_part stores visible

    // Parallel gather: thread t (t<128) owns row t of g_part -> registers.
    float r[NBITS + 1];
    if (tid < NBLOCKS) {
#pragma unroll
        for (int b = 0; b <= NBITS; b++) r[b] = g_part[tid][b];
    } else {
#pragma unroll
        for (int b = 0; b <= NBITS; b++) r[b] = 0.0f;
    }
#pragma unroll
    for (int b = 0; b <= NBITS; b++) red[tid][b] = r[b];

    // fp32 logs in parallel (warp-level, matches reference fp32 log)
    __shared__ float lp[NBITS], l1[NBITS];
    if (tid < NBITS) {
        float pp = yprob[tid];
        lp[tid] = logf(pp);
        l1[tid] = logf(1.0f - pp);
    }
    __syncthreads();

#pragma unroll
    for (int s = NBLOCKS / 2; s >= 1; s >>= 1) {
        if (tid < s) {
#pragma unroll
            for (int b = 0; b <= NBITS; b++) red[tid][b] += red[tid + s][b];
        }
        __syncthreads();
    }

    if (tid == 0) {
        int y_nonzero = 1;
        if (has_Y) y_nonzero = (Yp[0] != 0);

        double basee = 0.0;
#pragma unroll
        for (int j = 0; j < NBITS; j++) basee += (double)l1[j];

        if (y_nonzero) {
            double res = basee * (double)red[0][NBITS];
#pragma unroll
            for (int b = 0; b < NBITS; b++) {
                int j = NBITS - 1 - b;   // column j <-> bit (NBITS-1-j) of subset index
                res += ((double)lp[j] - (double)l1[j]) * (double)red[0][b];
            }
            out[0] = (float)res;
        } else {
            out[0] = (float)((double)NSUB * basee);
        }
    }
}

extern "C" void kernel_launch(void* const* d_in, const int* in_sizes, int n_in,
                              void* d_out, int out_size) {
    const float* yprob = (const float*)d_in[0];
    const float* w     = (const float*)d_in[1];
    const int*   Yp    = (n_in >= 3) ? (const int*)d_in[2] : nullptr;
    float*       out   = (float*)d_out;
    (void)in_sizes; (void)out_size;

    mil_fused_kernel<<<NBLOCKS, NTPB>>>(w, yprob, Yp, Yp != nullptr ? 1 : 0, out);
}